// round 7
// baseline (speedup 1.0000x reference)
#include <cuda_runtime.h>
#include <math.h>

#define B 32
#define H 512
#define W 512
#define C4 (W / 4)            // 128 float4 per row
#define KS 31
#define PAD 15
#define IMG4 (H * C4)
#define STRIPS 32
#define ROWS (H / STRIPS)      // 16 rows per block
#define ROUNDS (ROWS / 2)      // 8 rounds of 2 rows
#define NBLOCKS (B * STRIPS)   // 1024

// Per-block partials: [b][strip][4] = {wsum, wbce_num, inter, union}
__device__ float g_part[NBLOCKS * 4];
__device__ unsigned int g_ctr;   // zero-init; last block resets for graph replay

__inline__ __device__ float warp_reduce(float v) {
    #pragma unroll
    for (int o = 16; o > 0; o >>= 1) v += __shfl_down_sync(0xffffffffu, v, o);
    return v;
}

// two interleaved inclusive warp scans (ILP on the shfl chain)
__inline__ __device__ void warp_iscan2(float& a, float& b, int lane) {
    #pragma unroll
    for (int o = 1; o < 32; o <<= 1) {
        const float na = __shfl_up_sync(0xffffffffu, a, o);
        const float nb = __shfl_up_sync(0xffffffffu, b, o);
        if (lane >= o) { a += na; b += nb; }
    }
}

__inline__ __device__ float4 f4add(float4 a, float4 b) {
    return make_float4(a.x + b.x, a.y + b.y, a.z + b.z, a.w + b.w);
}
__inline__ __device__ float4 f4sub(float4 a, float4 b) {
    return make_float4(a.x - b.x, a.y - b.y, a.z - b.z, a.w - b.w);
}

__global__ void __launch_bounds__(128, 7)
fused_loss_kernel(const float4* __restrict__ pred,
                  const float4* __restrict__ target,
                  float* __restrict__ out) {
    const int strip = blockIdx.x;
    const int b     = blockIdx.y;
    const int w     = threadIdx.x;          // float4-column index, 0..127
    const int lane  = w & 31;
    const int wid   = w >> 5;
    const int r0    = strip * ROWS;

    const float4* t = target + b * IMG4;
    const float4* p = pred   + b * IMG4;

    // sP[buf][row-in-pair]: idx u+4 holds P4[u]; [0..3]=zeros, [132..135]=row total
    __shared__ float4 sP[2][2][136];
    __shared__ float  s_warp[2][2][4];
    __shared__ float  s_red[4][4];

    if (w < 16) {
        sP[(w >> 3) & 1][(w >> 2) & 1][w & 3] = make_float4(0.f, 0.f, 0.f, 0.f);
    }

    // Vertical sliding window: entering row r, sum4 = rows [r-15, r+14] (clamped)
    float4 sum4 = make_float4(0.f, 0.f, 0.f, 0.f);
    {
        int hlo = r0 - PAD; if (hlo < 0) hlo = 0;
        int hhi = r0 + PAD; if (hhi > H) hhi = H;
        #pragma unroll 5
        for (int h = hlo; h < hhi; ++h) sum4 = f4add(sum4, t[h * C4 + w]);
    }

    float acc0 = 0.f, acc1 = 0.f, acc2 = 0.f, acc3 = 0.f;
    const float inv = 1.0f / (KS * KS);
    const float4 zero4 = make_float4(0.f, 0.f, 0.f, 0.f);

    for (int g = 0; g < ROUNDS; ++g) {
        const int r   = r0 + 2 * g;
        const int buf = g & 1;

        // ---- front-batched loads for both rows (overlap with scan below) ----
        const float4 a0  = (r + PAD < H)     ? t[(r + PAD) * C4 + w]     : zero4;
        const float4 a1  = (r + 1 + PAD < H) ? t[(r + 1 + PAD) * C4 + w] : zero4;
        const float4 s0  = (r - PAD >= 0)    ? t[(r - PAD) * C4 + w]     : zero4;
        const float4 s1  = (r + 1 - PAD >= 0)? t[(r + 1 - PAD) * C4 + w] : zero4;
        const float4 tg0 = t[r * C4 + w];
        const float4 tg1 = t[(r + 1) * C4 + w];
        const float4 x0  = p[r * C4 + w];
        const float4 x1  = p[(r + 1) * C4 + w];

        // ---- vertical sums for both rows ----
        sum4 = f4add(sum4, a0);
        const float4 vs0 = sum4;
        sum4 = f4sub(sum4, s0);
        sum4 = f4add(sum4, a1);
        const float4 vs1 = sum4;
        sum4 = f4sub(sum4, s1);

        // ---- thread-local prefixes ----
        const float q0a = vs0.x, q1a = q0a + vs0.y, q2a = q1a + vs0.z, q3a = q2a + vs0.w;
        const float q0b = vs1.x, q1b = q0b + vs1.y, q2b = q1b + vs1.z, q3b = q2b + vs1.w;

        // ---- interleaved warp scans of thread totals ----
        float ia = q3a, ib = q3b;
        warp_iscan2(ia, ib, lane);
        const float exa = ia - q3a;
        const float exb = ib - q3b;
        if (lane == 31) {
            s_warp[buf][0][wid] = ia;
            s_warp[buf][1][wid] = ib;
        }
        __syncthreads();

        const float w0a = s_warp[buf][0][0], w1a = s_warp[buf][0][1];
        const float w2a = s_warp[buf][0][2], w3a = s_warp[buf][0][3];
        const float w0b = s_warp[buf][1][0], w1b = s_warp[buf][1][1];
        const float w2b = s_warp[buf][1][2], w3b = s_warp[buf][1][3];

        const float offa = (wid > 0 ? w0a : 0.f) + (wid > 1 ? w1a : 0.f) + (wid > 2 ? w2a : 0.f);
        const float offb = (wid > 0 ? w0b : 0.f) + (wid > 1 ? w1b : 0.f) + (wid > 2 ? w2b : 0.f);
        const float basea = offa + exa;
        const float baseb = offb + exb;

        sP[buf][0][w + 4] = make_float4(basea + q0a, basea + q1a, basea + q2a, basea + q3a);
        sP[buf][1][w + 4] = make_float4(baseb + q0b, baseb + q1b, baseb + q2b, baseb + q3b);
        if (w < 4) {
            const float tota = w0a + w1a + w2a + w3a;
            const float totb = w0b + w1b + w2b + w3b;
            sP[buf][0][132 + w] = make_float4(tota, tota, tota, tota);
            sP[buf][1][132 + w] = make_float4(totb, totb, totb, totb);
        }
        __syncthreads();

        // ---- taps + elementwise loss for both rows ----
        #pragma unroll
        for (int j = 0; j < 2; ++j) {
            const float4 lo = sP[buf][j][w];
            const float4 A  = sP[buf][j][w + 7];
            const float4 Bv = sP[buf][j][w + 8];
            const float4 tg = j ? tg1 : tg0;
            const float4 xq = j ? x1 : x0;

            float box[4], tgv[4], x[4];
            box[0] = (A.w  - lo.x) * inv;
            box[1] = (Bv.x - lo.y) * inv;
            box[2] = (Bv.y - lo.z) * inv;
            box[3] = (Bv.z - lo.w) * inv;
            tgv[0] = tg.x; tgv[1] = tg.y; tgv[2] = tg.z; tgv[3] = tg.w;
            x[0] = xq.x; x[1] = xq.y; x[2] = xq.z; x[3] = xq.w;

            #pragma unroll
            for (int k = 0; k < 4; ++k) {
                const float weit = 1.0f + 5.0f * fabsf(box[k] - tgv[k]);
                const float e    = __expf(-fabsf(x[k]));
                const float lg   = __logf(1.0f + e);
                const float bce  = fmaxf(x[k], 0.0f) - x[k] * tgv[k] + lg;
                const float invs = __fdividef(1.0f, 1.0f + e);
                const float pr   = (x[k] >= 0.0f) ? invs : 1.0f - invs;

                acc0 += weit;
                acc1 += weit * bce;
                acc2 += pr * tgv[k] * weit;
                acc3 += (pr + tgv[k]) * weit;
            }
        }
        // no third barrier: round g+1 uses the other buffer; its two barriers
        // fence round g's reads from round g+2's writes.
    }

    // ---- block reduction (4 warps) ----
    float vals[4] = {acc0, acc1, acc2, acc3};
    #pragma unroll
    for (int k = 0; k < 4; ++k) {
        const float v = warp_reduce(vals[k]);
        if (lane == 0) s_red[k][wid] = v;
    }
    __syncthreads();

    if (wid == 0) {
        float v[4];
        #pragma unroll
        for (int k = 0; k < 4; ++k) {
            float vv = (lane < 4) ? s_red[k][lane] : 0.f;
            #pragma unroll
            for (int o = 2; o > 0; o >>= 1) vv += __shfl_down_sync(0xffffffffu, vv, o);
            v[k] = vv;
        }
        if (lane == 0) {
            #pragma unroll
            for (int k = 0; k < 4; ++k)
                g_part[(b * STRIPS + strip) * 4 + k] = v[k];
            __threadfence();
        }
        __syncwarp();

        unsigned int ticket = 0;
        if (lane == 0) ticket = atomicAdd(&g_ctr, 1u);
        ticket = __shfl_sync(0xffffffffu, ticket, 0);
        if (ticket == NBLOCKS - 1) {
            // lane = image index (32 lanes, 32 images)
            float wsum = 0.f, wbce_n = 0.f, inter = 0.f, uni = 0.f;
            #pragma unroll 4
            for (int s = 0; s < STRIPS; ++s) {
                const float* pp = &g_part[(lane * STRIPS + s) * 4];
                wsum   += pp[0];
                wbce_n += pp[1];
                inter  += pp[2];
                uni    += pp[3];
            }
            const float wbce = wbce_n / wsum;
            const float wiou = 1.0f - (inter + 1.0f) / (uni - inter + 1.0f);
            float loss = warp_reduce(wbce + wiou);
            if (lane == 0) {
                out[0] = loss * (1.0f / B);
                g_ctr = 0;   // reset for graph replay
            }
        }
    }
}

extern "C" void kernel_launch(void* const* d_in, const int* in_sizes, int n_in,
                              void* d_out, int out_size) {
    const float4* pred   = (const float4*)d_in[0];
    const float4* target = (const float4*)d_in[1];
    float* out = (float*)d_out;

    dim3 grid(STRIPS, B);
    fused_loss_kernel<<<grid, 128>>>(pred, target, out);
}

// round 8
// speedup vs baseline: 1.0106x; 1.0106x over previous
#include <cuda_runtime.h>
#include <math.h>

#define B 32
#define H 512
#define W 512
#define C4 (W / 4)            // 128 float4 per row
#define KS 31
#define PAD 15
#define IMG4 (H * C4)
#define STRIPS 32
#define ROWS (H / STRIPS)      // 16 rows per block
#define ROUNDS (ROWS / 2)      // 8 rounds of 2 rows
#define NBLOCKS (B * STRIPS)   // 1024

// Per-block partials: [b][strip][4] = {wsum, wbce_num, inter, union}
__device__ float g_part[NBLOCKS * 4];
__device__ unsigned int g_ctr;   // zero-init; last block resets for graph replay

__inline__ __device__ float warp_reduce(float v) {
    #pragma unroll
    for (int o = 16; o > 0; o >>= 1) v += __shfl_down_sync(0xffffffffu, v, o);
    return v;
}

// two interleaved inclusive warp scans (ILP on the shfl chain)
__inline__ __device__ void warp_iscan2(float& a, float& b, int lane) {
    #pragma unroll
    for (int o = 1; o < 32; o <<= 1) {
        const float na = __shfl_up_sync(0xffffffffu, a, o);
        const float nb = __shfl_up_sync(0xffffffffu, b, o);
        if (lane >= o) { a += na; b += nb; }
    }
}

__inline__ __device__ float4 f4add(float4 a, float4 b) {
    return make_float4(a.x + b.x, a.y + b.y, a.z + b.z, a.w + b.w);
}
__inline__ __device__ float4 f4sub(float4 a, float4 b) {
    return make_float4(a.x - b.x, a.y - b.y, a.z - b.z, a.w - b.w);
}

__global__ void __launch_bounds__(128, 7)
fused_loss_kernel(const float4* __restrict__ pred,
                  const float4* __restrict__ target,
                  float* __restrict__ out) {
    const int strip = blockIdx.x;
    const int b     = blockIdx.y;
    const int w     = threadIdx.x;          // float4-column index, 0..127
    const int lane  = w & 31;
    const int wid   = w >> 5;
    const int r0    = strip * ROWS;

    const float4* t = target + b * IMG4;
    const float4* p = pred   + b * IMG4;

    // sP[buf][row-in-pair]: idx u+4 holds P4[u]; [0..3]=zeros, [132..135]=row total
    __shared__ float4 sP[2][2][136];
    __shared__ float  s_warp[2][2][4];
    __shared__ float  s_red[4][4];

    if (w < 16) {
        sP[(w >> 3) & 1][(w >> 2) & 1][w & 3] = make_float4(0.f, 0.f, 0.f, 0.f);
    }

    // Vertical sliding window: entering row r, sum4 = rows [r-15, r+14] (clamped)
    float4 sum4 = make_float4(0.f, 0.f, 0.f, 0.f);
    {
        int hlo = r0 - PAD; if (hlo < 0) hlo = 0;
        int hhi = r0 + PAD; if (hhi > H) hhi = H;
        #pragma unroll 5
        for (int h = hlo; h < hhi; ++h) sum4 = f4add(sum4, t[h * C4 + w]);
    }

    float acc0 = 0.f, acc1 = 0.f, acc2 = 0.f, acc3 = 0.f;
    const float inv = 1.0f / (KS * KS);
    const float4 zero4 = make_float4(0.f, 0.f, 0.f, 0.f);

    for (int g = 0; g < ROUNDS; ++g) {
        const int r   = r0 + 2 * g;
        const int buf = g & 1;

        // ---- front-batched loads for both rows (overlap with scan below) ----
        const float4 a0  = (r + PAD < H)     ? t[(r + PAD) * C4 + w]     : zero4;
        const float4 a1  = (r + 1 + PAD < H) ? t[(r + 1 + PAD) * C4 + w] : zero4;
        const float4 s0  = (r - PAD >= 0)    ? t[(r - PAD) * C4 + w]     : zero4;
        const float4 s1  = (r + 1 - PAD >= 0)? t[(r + 1 - PAD) * C4 + w] : zero4;
        const float4 tg0 = t[r * C4 + w];
        const float4 tg1 = t[(r + 1) * C4 + w];
        const float4 x0  = p[r * C4 + w];
        const float4 x1  = p[(r + 1) * C4 + w];

        // ---- vertical sums for both rows ----
        sum4 = f4add(sum4, a0);
        const float4 vs0 = sum4;
        sum4 = f4sub(sum4, s0);
        sum4 = f4add(sum4, a1);
        const float4 vs1 = sum4;
        sum4 = f4sub(sum4, s1);

        // ---- thread-local prefixes ----
        const float q0a = vs0.x, q1a = q0a + vs0.y, q2a = q1a + vs0.z, q3a = q2a + vs0.w;
        const float q0b = vs1.x, q1b = q0b + vs1.y, q2b = q1b + vs1.z, q3b = q2b + vs1.w;

        // ---- interleaved warp scans of thread totals ----
        float ia = q3a, ib = q3b;
        warp_iscan2(ia, ib, lane);
        const float exa = ia - q3a;
        const float exb = ib - q3b;
        if (lane == 31) {
            s_warp[buf][0][wid] = ia;
            s_warp[buf][1][wid] = ib;
        }
        __syncthreads();

        const float w0a = s_warp[buf][0][0], w1a = s_warp[buf][0][1];
        const float w2a = s_warp[buf][0][2], w3a = s_warp[buf][0][3];
        const float w0b = s_warp[buf][1][0], w1b = s_warp[buf][1][1];
        const float w2b = s_warp[buf][1][2], w3b = s_warp[buf][1][3];

        const float offa = (wid > 0 ? w0a : 0.f) + (wid > 1 ? w1a : 0.f) + (wid > 2 ? w2a : 0.f);
        const float offb = (wid > 0 ? w0b : 0.f) + (wid > 1 ? w1b : 0.f) + (wid > 2 ? w2b : 0.f);
        const float basea = offa + exa;
        const float baseb = offb + exb;

        sP[buf][0][w + 4] = make_float4(basea + q0a, basea + q1a, basea + q2a, basea + q3a);
        sP[buf][1][w + 4] = make_float4(baseb + q0b, baseb + q1b, baseb + q2b, baseb + q3b);
        if (w < 4) {
            const float tota = w0a + w1a + w2a + w3a;
            const float totb = w0b + w1b + w2b + w3b;
            sP[buf][0][132 + w] = make_float4(tota, tota, tota, tota);
            sP[buf][1][132 + w] = make_float4(totb, totb, totb, totb);
        }
        __syncthreads();

        // ---- taps + elementwise loss for both rows ----
        #pragma unroll
        for (int j = 0; j < 2; ++j) {
            const float4 lo = sP[buf][j][w];
            const float4 A  = sP[buf][j][w + 7];
            const float4 Bv = sP[buf][j][w + 8];
            const float4 tg = j ? tg1 : tg0;
            const float4 xq = j ? x1 : x0;

            float box[4], tgv[4], x[4];
            box[0] = (A.w  - lo.x) * inv;
            box[1] = (Bv.x - lo.y) * inv;
            box[2] = (Bv.y - lo.z) * inv;
            box[3] = (Bv.z - lo.w) * inv;
            tgv[0] = tg.x; tgv[1] = tg.y; tgv[2] = tg.z; tgv[3] = tg.w;
            x[0] = xq.x; x[1] = xq.y; x[2] = xq.z; x[3] = xq.w;

            #pragma unroll
            for (int k = 0; k < 4; ++k) {
                const float weit = 1.0f + 5.0f * fabsf(box[k] - tgv[k]);
                const float e    = __expf(-fabsf(x[k]));
                const float lg   = __logf(1.0f + e);
                const float bce  = fmaxf(x[k], 0.0f) - x[k] * tgv[k] + lg;
                const float invs = __fdividef(1.0f, 1.0f + e);
                const float pr   = (x[k] >= 0.0f) ? invs : 1.0f - invs;

                acc0 += weit;
                acc1 += weit * bce;
                acc2 += pr * tgv[k] * weit;
                acc3 += (pr + tgv[k]) * weit;
            }
        }
        // no third barrier: round g+1 uses the other buffer; its two barriers
        // fence round g's reads from round g+2's writes.
    }

    // ---- block reduction (4 warps) ----
    float vals[4] = {acc0, acc1, acc2, acc3};
    #pragma unroll
    for (int k = 0; k < 4; ++k) {
        const float v = warp_reduce(vals[k]);
        if (lane == 0) s_red[k][wid] = v;
    }
    __syncthreads();

    if (wid == 0) {
        float v[4];
        #pragma unroll
        for (int k = 0; k < 4; ++k) {
            float vv = (lane < 4) ? s_red[k][lane] : 0.f;
            #pragma unroll
            for (int o = 2; o > 0; o >>= 1) vv += __shfl_down_sync(0xffffffffu, vv, o);
            v[k] = vv;
        }
        if (lane == 0) {
            #pragma unroll
            for (int k = 0; k < 4; ++k)
                g_part[(b * STRIPS + strip) * 4 + k] = v[k];
            __threadfence();
        }
        __syncwarp();

        unsigned int ticket = 0;
        if (lane == 0) ticket = atomicAdd(&g_ctr, 1u);
        ticket = __shfl_sync(0xffffffffu, ticket, 0);
        if (ticket == NBLOCKS - 1) {
            // lane = image index (32 lanes, 32 images)
            float wsum = 0.f, wbce_n = 0.f, inter = 0.f, uni = 0.f;
            #pragma unroll 4
            for (int s = 0; s < STRIPS; ++s) {
                const float* pp = &g_part[(lane * STRIPS + s) * 4];
                wsum   += pp[0];
                wbce_n += pp[1];
                inter  += pp[2];
                uni    += pp[3];
            }
            const float wbce = wbce_n / wsum;
            const float wiou = 1.0f - (inter + 1.0f) / (uni - inter + 1.0f);
            float loss = warp_reduce(wbce + wiou);
            if (lane == 0) {
                out[0] = loss * (1.0f / B);
                g_ctr = 0;   // reset for graph replay
            }
        }
    }
}

extern "C" void kernel_launch(void* const* d_in, const int* in_sizes, int n_in,
                              void* d_out, int out_size) {
    const float4* pred   = (const float4*)d_in[0];
    const float4* target = (const float4*)d_in[1];
    float* out = (float*)d_out;

    dim3 grid(STRIPS, B);
    fused_loss_kernel<<<grid, 128>>>(pred, target, out);
}